// round 13
// baseline (speedup 1.0000x reference)
#include <cuda_runtime.h>
#include <cuda_fp16.h>
#include <cstdint>

#define BSZ 32
#define CNT 128
#define Wd  2048
#define Pd  1024
#define Ed  8
#define Kc  25
#define Ld  2
#define ROWS (BSZ*CNT)   // 4096

// ---------------- scratch ----------------
__device__ float  g_x[ROWS*Wd];
__device__ __half g_ch[ROWS*Wd];
__device__ __half g_cm[ROWS*Wd];
__device__ float  g_qkv[3*ROWS*Pd];
__device__ __half g_ph[ROWS*Pd];
__device__ __half g_pm[ROWS*Pd];
__device__ __half g_wqkv[3*Ld*Pd*Wd];
__device__ __half g_wo[Ld*Wd*Pd];
__device__ float  g_bqkv[3*Ld*Pd];
__device__ float  g_wavg[Ld*Kc];
__device__ float  g_bavg[Ld];

// ---------------- helpers ----------------
__device__ __forceinline__ uint32_t smem_u32(const void* p) {
    uint32_t a;
    asm("{ .reg .u64 t; cvta.to.shared.u64 t, %1; cvt.u32.u64 %0, t; }" : "=r"(a) : "l"(p));
    return a;
}
__device__ __forceinline__ void cp16(uint32_t dst, const void* src) {
    asm volatile("cp.async.cg.shared.global [%0], [%1], 16;" :: "r"(dst), "l"(src));
}
__device__ __forceinline__ void split2h(float x, __half& h, __half& m) {
    h = __float2half(x);
    m = __float2half(x - __half2float(h));
}
__device__ __forceinline__ uint32_t pack2h(__half a, __half b) {
    return (uint32_t)__half_as_ushort(a) | ((uint32_t)__half_as_ushort(b) << 16);
}
__device__ __forceinline__ float2 cmulf(float2 a, float2 b) {
    return make_float2(a.x * b.x - a.y * b.y, a.x * b.y + a.y * b.x);
}

// ---------------- weight convert fp32 -> fp16 (all 4 matrices, one launch) ----------------
__global__ void cvt16_all_kernel(const float* __restrict__ wq, const float* __restrict__ wk,
                                 const float* __restrict__ wv, const float* __restrict__ wo,
                                 __half* __restrict__ wqkv, __half* __restrict__ wod, int n8) {
    int i = blockIdx.x * blockDim.x + threadIdx.x;
    int stride = gridDim.x * blockDim.x;
    for (; i < 4 * n8; i += stride) {
        int sel = i / n8, j = i - sel * n8;
        const float* src = (sel == 0) ? wq : (sel == 1) ? wk : (sel == 2) ? wv : wo;
        __half* dst = (sel < 3) ? (wqkv + (size_t)sel * n8 * 8) : wod;
        float4 v0 = ((const float4*)src)[2 * j];
        float4 v1 = ((const float4*)src)[2 * j + 1];
        uint4 u;
        u.x = pack2h(__float2half(v0.x), __float2half(v0.y));
        u.y = pack2h(__float2half(v0.z), __float2half(v0.w));
        u.z = pack2h(__float2half(v1.x), __float2half(v1.y));
        u.w = pack2h(__float2half(v1.z), __float2half(v1.w));
        ((uint4*)dst)[j] = u;
    }
}

// ---------------- avg conv weights ----------------
__global__ void avg_conv_kernel(const float* __restrict__ cw, const float* __restrict__ cb,
                                float* __restrict__ wavg, float* __restrict__ bavg) {
    int idx = threadIdx.x;
    if (idx < Ld * Kc) {
        int l = idx / Kc, kk = idx % Kc;
        float s = 0.f;
        #pragma unroll
        for (int e = 0; e < Ed; e++) s += cw[(l * Ed + e) * Kc + kk];
        wavg[idx] = s * (1.0f / Ed);
    }
    if (idx < Ld) {
        float s = 0.f;
        #pragma unroll
        for (int e = 0; e < Ed; e++) s += cb[idx * Ed + e];
        bavg[idx] = s * (1.0f / Ed);
    }
}

// ---------------- 1D conv, writes fp16 h/m ----------------
__global__ __launch_bounds__(256) void conv_row_kernel(
    const float* __restrict__ X, __half* __restrict__ Yh, __half* __restrict__ Ym,
    const float* __restrict__ wavg, const float* __restrict__ bavg)
{
    __shared__ float sx[Wd + Kc - 1];
    __shared__ float wsh[Kc];
    const int row = blockIdx.x;
    const int tid = threadIdx.x;
    const float* xr = X + (size_t)row * Wd;

    for (int i = tid; i < Wd + Kc - 1; i += 256) {
        int src = i - (Kc / 2);
        sx[i] = (src >= 0 && src < Wd) ? xr[src] : 0.0f;
    }
    if (tid < Kc) wsh[tid] = wavg[tid];
    __syncthreads();

    const float b = bavg[0];
    __half* yh = Yh + (size_t)row * Wd;
    __half* ym = Ym + (size_t)row * Wd;
    for (int h = tid; h < Wd; h += 256) {
        float s = b;
        #pragma unroll
        for (int k = 0; k < Kc; k++) s += sx[h + k] * wsh[k];
        __half sh, sm_;
        split2h(s, sh, sm_);
        yh[h] = sh; ym[h] = sm_;
    }
}

// ---------------- common GEMM macros ----------------
#define MMA16(cc, aa, bb) \
    asm volatile("mma.sync.aligned.m16n8k16.row.col.f32.f16.f16.f32 " \
        "{%0,%1,%2,%3},{%4,%5,%6,%7},{%8,%9},{%0,%1,%2,%3};" \
        : "+f"((cc)[0]), "+f"((cc)[1]), "+f"((cc)[2]), "+f"((cc)[3]) \
        : "r"((aa)[0]), "r"((aa)[1]), "r"((aa)[2]), "r"((aa)[3]), \
          "r"((bb)[0]), "r"((bb)[1]))

#define LDMX4(r0, r1, r2, r3, a) \
    asm volatile("ldmatrix.sync.aligned.m8n8.x4.shared.b16 {%0,%1,%2,%3}, [%4];" \
        : "=r"(r0), "=r"(r1), "=r"(r2), "=r"(r3) : "r"(a))

#define BK 32

// ================= fused q/k/v GEMM: tile 128 x (64 per z), 3 z =================
#define QA_W 2048              // A tile: 128 rows x 16 words
#define QW_W 1024              // W tile: 64 rows x 16 words
#define QSTAGE_W (2*QA_W + 3*QW_W)   // 7168 words = 28KB
#define QNSTAGE 3
#define QGEMM_SMEM (QNSTAGE*QSTAGE_W*4)   // 86016 bytes

__global__ __launch_bounds__(256, 2) void gemm_qkv_kernel(
    const __half* __restrict__ Ah, const __half* __restrict__ Am,
    const __half* __restrict__ Wq,          // 3 matrices, stride szB
    const float* __restrict__ bias,         // 3 biases, stride Ld*Pd
    float* __restrict__ C,                  // 3 outputs, stride RP
    size_t szB)
{
    extern __shared__ uint32_t sm[];
    const uint32_t sbase = smem_u32(sm);
    const int Kd = Wd, N = Pd;

    const int tid = threadIdx.x;
    const int wid = tid >> 5, lane = tid & 31;
    const int g = lane >> 2, t = lane & 3;
    const int wm = (wid >> 1) * 32;       // 4 m-groups x 32 rows
    const int wn = (wid & 1) * 32;        // 2 n-groups x 32 cols (within 64)
    const int bm = blockIdx.y * 128, bn = blockIdx.x * 64;
    const int stA = wid & 1;

    const int lr = lane & 7;
    const int ls = lane >> 3;
    uint32_t Abase[2], Bbase[2];
    #pragma unroll
    for (int st = 0; st < 2; st++) {
        int arow = wm + lr + (ls & 1) * 8;
        int awc2 = st * 2 + (ls >> 1);
        Abase[st] = (uint32_t)(arow * 16 + ((awc2 ^ ((arow >> 1) & 3)) << 2)) * 4;
        int brow = wn + (ls >> 1) * 8 + lr;
        int bwc2 = st * 2 + (ls & 1);
        Bbase[st] = (uint32_t)(brow * 16 + ((bwc2 ^ ((brow >> 1) & 3)) << 2)) * 4;
    }

    // cp.async mapping
    const int r0 = tid >> 2, c0 = tid & 3;          // A: rows r0, r0+64
    const int r1 = r0 + 64;
    const uint32_t d0 = (uint32_t)(r0 * 16 + ((c0 ^ ((r0 >> 1) & 3)) << 2)) * 4;
    const uint32_t d1 = (uint32_t)(r1 * 16 + ((c0 ^ ((r1 >> 1) & 3)) << 2)) * 4;
    const uint32_t dW = d0;                          // W: row r0 (0..63), same swizzle

    const uint32_t offA0 = (uint32_t)(bm + r0) * Kd + c0 * 8;
    const uint32_t offA1 = (uint32_t)(bm + r1) * Kd + c0 * 8;
    const uint32_t offW  = (uint32_t)(bn + r0) * Kd + c0 * 8;   // r0<64 covers W tile

    float acc[3][2][4][4];
    #pragma unroll
    for (int z = 0; z < 3; z++)
        #pragma unroll
        for (int mt = 0; mt < 2; mt++)
            #pragma unroll
            for (int nt = 0; nt < 4; nt++)
                #pragma unroll
                for (int e = 0; e < 4; e++) acc[z][mt][nt][e] = 0.0f;

    const int NC = Kd / BK;

    #define QISSUE(s, kpos) do { \
        uint32_t _sb = sbase + (uint32_t)(s) * (QSTAGE_W * 4); \
        cp16(_sb + d0,              Ah + offA0 + (kpos)); \
        cp16(_sb + d1,              Ah + offA1 + (kpos)); \
        cp16(_sb + QA_W * 4 + d0,   Am + offA0 + (kpos)); \
        cp16(_sb + QA_W * 4 + d1,   Am + offA1 + (kpos)); \
        cp16(_sb + 2 * QA_W * 4 + dW,                 Wq + offW + (kpos)); \
        cp16(_sb + 2 * QA_W * 4 + QW_W * 4 + dW,      Wq + szB + offW + (kpos)); \
        cp16(_sb + 2 * QA_W * 4 + 2 * QW_W * 4 + dW,  Wq + 2 * szB + offW + (kpos)); \
        asm volatile("cp.async.commit_group;" ::: "memory"); \
    } while (0)

    QISSUE(0, 0);
    QISSUE(1, BK);

    for (int i = 0; i < NC; i++) {
        if (i + 1 < NC) asm volatile("cp.async.wait_group 1;" ::: "memory");
        else            asm volatile("cp.async.wait_group 0;" ::: "memory");
        __syncthreads();
        if (i + 2 < NC) {
            int s = i + 2; s = s - (s / 3) * 3;
            QISSUE(s, (i + 2) * BK);
        }

        int bsel = i - (i / 3) * 3;
        const uint32_t sAh = sbase + (uint32_t)bsel * (QSTAGE_W * 4);
        const uint32_t sAm = sAh + QA_W * 4;
        const uint32_t sW0 = sAm + QA_W * 4;

        #pragma unroll
        for (int s = 0; s < 2; s++) {
            const int st = s ^ stA;
            const uint32_t ab = Abase[st];
            const uint32_t bb = Bbase[st];

            uint32_t ah[2][4], am_[2][4];
            LDMX4(ah[0][0], ah[0][1], ah[0][2], ah[0][3], sAh + ab);
            LDMX4(ah[1][0], ah[1][1], ah[1][2], ah[1][3], sAh + ab + 1024);
            LDMX4(am_[0][0], am_[0][1], am_[0][2], am_[0][3], sAm + ab);
            LDMX4(am_[1][0], am_[1][1], am_[1][2], am_[1][3], sAm + ab + 1024);

            #pragma unroll
            for (int z = 0; z < 3; z++) {
                const uint32_t sWz = sW0 + (uint32_t)z * (QW_W * 4);
                uint32_t bw[4][2];
                LDMX4(bw[0][0], bw[0][1], bw[1][0], bw[1][1], sWz + bb);
                LDMX4(bw[2][0], bw[2][1], bw[3][0], bw[3][1], sWz + bb + 1024);
                #pragma unroll
                for (int mt = 0; mt < 2; mt++)
                    #pragma unroll
                    for (int nt = 0; nt < 4; nt++) {
                        MMA16(acc[z][mt][nt], ah[mt],  bw[nt]);
                        MMA16(acc[z][mt][nt], am_[mt], bw[nt]);
                    }
            }
        }
        __syncthreads();
    }
    #undef QISSUE

    // epilogue
    #pragma unroll
    for (int z = 0; z < 3; z++) {
        const float* bz = bias + (size_t)z * (Ld * Pd);
        float* Cz = C + (size_t)z * ((size_t)ROWS * Pd);
        #pragma unroll
        for (int mt = 0; mt < 2; mt++) {
            #pragma unroll
            for (int nt = 0; nt < 4; nt++) {
                int col = bn + wn + nt * 8 + 2 * t;
                float b0 = __ldg(&bz[col]);
                float b1 = __ldg(&bz[col + 1]);
                float* p0 = Cz + (size_t)(bm + wm + mt * 16 + g) * N + col;
                float2 o0 = make_float2(acc[z][mt][nt][0] + b0, acc[z][mt][nt][1] + b1);
                float2 o1 = make_float2(acc[z][mt][nt][2] + b0, acc[z][mt][nt][3] + b1);
                *(float2*)p0 = o0;
                *(float2*)(p0 + 8 * N) = o1;
            }
        }
    }
}

// ================= wo GEMM (round-12 kernel, 32x64 warp tile) =================
#define TILE_W 2048
#define STAGE_W (3*TILE_W)
#define NSTAGE 3
#define GEMM_SMEM (NSTAGE*STAGE_W*4)   // 73728 bytes

__global__ __launch_bounds__(256, 2) void gemm_wo_kernel(
    const __half* __restrict__ Ah, const __half* __restrict__ Am,
    const __half* __restrict__ Bw,
    const float* __restrict__ bias, float* __restrict__ C,
    int Kd, int N)
{
    extern __shared__ uint32_t sm[];
    const uint32_t sbase = smem_u32(sm);

    const int tid = threadIdx.x;
    const int wid = tid >> 5, lane = tid & 31;
    const int g = lane >> 2, t = lane & 3;
    const int wm = (wid >> 1) * 32;
    const int wn = (wid & 1) * 64;
    const int bm = blockIdx.y * 128, bn = blockIdx.x * 128;
    const int stA = wid & 1;

    const int lr = lane & 7;
    const int ls = lane >> 3;
    uint32_t Abase[2], Bbase[2];
    #pragma unroll
    for (int st = 0; st < 2; st++) {
        int arow = wm + lr + (ls & 1) * 8;
        int awc2 = st * 2 + (ls >> 1);
        Abase[st] = (uint32_t)(arow * 16 + ((awc2 ^ ((arow >> 1) & 3)) << 2)) * 4;
        int brow = wn + (ls >> 1) * 8 + lr;
        int bwc2 = st * 2 + (ls & 1);
        Bbase[st] = (uint32_t)(brow * 16 + ((bwc2 ^ ((brow >> 1) & 3)) << 2)) * 4;
    }

    const int r0 = tid >> 2, c0 = tid & 3;
    const int r1 = r0 + 64;
    const uint32_t d0 = (uint32_t)(r0 * 16 + ((c0 ^ ((r0 >> 1) & 3)) << 2)) * 4;
    const uint32_t d1 = (uint32_t)(r1 * 16 + ((c0 ^ ((r1 >> 1) & 3)) << 2)) * 4;

    const __half* a0h = Ah + (size_t)(bm + r0) * Kd + c0 * 8;
    const __half* a0m = Am + (size_t)(bm + r0) * Kd + c0 * 8;
    const __half* a1h = Ah + (size_t)(bm + r1) * Kd + c0 * 8;
    const __half* a1m = Am + (size_t)(bm + r1) * Kd + c0 * 8;
    const __half* b0w = Bw + (size_t)(bn + r0) * Kd + c0 * 8;
    const __half* b1w = Bw + (size_t)(bn + r1) * Kd + c0 * 8;

    float acc[2][8][4];
    #pragma unroll
    for (int mt = 0; mt < 2; mt++)
        #pragma unroll
        for (int nt = 0; nt < 8; nt++)
            #pragma unroll
            for (int e = 0; e < 4; e++) acc[mt][nt][e] = 0.0f;

    const int NC = Kd / BK;

    #define ISSUE(s, kpos) do { \
        uint32_t _sb = sbase + (uint32_t)(s) * (STAGE_W * 4); \
        cp16(_sb + d0,                   a0h + (kpos)); \
        cp16(_sb + d1,                   a1h + (kpos)); \
        cp16(_sb + TILE_W * 4 + d0,      a0m + (kpos)); \
        cp16(_sb + TILE_W * 4 + d1,      a1m + (kpos)); \
        cp16(_sb + 2 * TILE_W * 4 + d0,  b0w + (kpos)); \
        cp16(_sb + 2 * TILE_W * 4 + d1,  b1w + (kpos)); \
        asm volatile("cp.async.commit_group;" ::: "memory"); \
    } while (0)

    ISSUE(0, 0);
    ISSUE(1, BK);

    for (int i = 0; i < NC; i++) {
        if (i + 1 < NC) asm volatile("cp.async.wait_group 1;" ::: "memory");
        else            asm volatile("cp.async.wait_group 0;" ::: "memory");
        __syncthreads();
        if (i + 2 < NC) {
            int s = i + 2; s = s - (s / 3) * 3;
            ISSUE(s, (i + 2) * BK);
        }

        int bsel = i - (i / 3) * 3;
        const uint32_t sAh = sbase + (uint32_t)bsel * (STAGE_W * 4);
        const uint32_t sAm = sAh + TILE_W * 4;
        const uint32_t sBw = sAm + TILE_W * 4;

        #pragma unroll
        for (int s = 0; s < 2; s++) {
            const int st = s ^ stA;
            const uint32_t ab = Abase[st];
            const uint32_t bb = Bbase[st];

            uint32_t bw[8][2];
            LDMX4(bw[0][0], bw[0][1], bw[1][0], bw[1][1], sBw + bb);
            LDMX4(bw[2][0], bw[2][1], bw[3][0], bw[3][1], sBw + bb + 1024);
            LDMX4(bw[4][0], bw[4][1], bw[5][0], bw[5][1], sBw + bb + 2048);
            LDMX4(bw[6][0], bw[6][1], bw[7][0], bw[7][1], sBw + bb + 3072);

            #pragma unroll
            for (int mt = 0; mt < 2; mt++) {
                uint32_t ah[4], am_[4];
                uint32_t ao = ab + (uint32_t)mt * 1024;
                LDMX4(ah[0], ah[1], ah[2], ah[3], sAh + ao);
                LDMX4(am_[0], am_[1], am_[2], am_[3], sAm + ao);
                #pragma unroll
                for (int nt = 0; nt < 8; nt++) {
                    MMA16(acc[mt][nt], ah,  bw[nt]);
                    MMA16(acc[mt][nt], am_, bw[nt]);
                }
            }
        }
        __syncthreads();
    }
    #undef ISSUE

    #pragma unroll
    for (int mt = 0; mt < 2; mt++) {
        #pragma unroll
        for (int nt = 0; nt < 8; nt++) {
            int col = bn + wn + nt * 8 + 2 * t;
            float b0 = __ldg(&bias[col]);
            float b1 = __ldg(&bias[col + 1]);
            float* p0 = C + (size_t)(bm + wm + mt * 16 + g) * N + col;
            float2 o0 = make_float2(acc[mt][nt][0] + b0, acc[mt][nt][1] + b1);
            float2 o1 = make_float2(acc[mt][nt][2] + b0, acc[mt][nt][3] + b1);
            *(float2*)p0 = o0;
            *(float2*)(p0 + 8 * N) = o1;
        }
    }
}

// ---------------- radix-4 FFT attention, 2 rows per block ----------------
__device__ __forceinline__ int rev4(int v) {
    return ((v & 3) << 8) | (((v >> 2) & 3) << 6) | (((v >> 4) & 3) << 4)
         | (((v >> 6) & 3) << 2) | ((v >> 8) & 3);
}

__device__ __forceinline__ void fft1024_r4(float2* s, const float2* Tw, int tid, bool inv) {
    #pragma unroll
    for (int stage = 0; stage < 5; ++stage) {
        const int q = 1 << (2 * stage);
        const int j = tid & (q - 1);
        const int grp = tid >> (2 * stage);
        const int i0 = grp * (q << 2) + j;
        const int i1 = i0 + q, i2 = i1 + q, i3 = i2 + q;

        float2 w1 = Tw[j << (8 - 2 * stage)];
        if (inv) w1.y = -w1.y;
        float2 w2 = cmulf(w1, w1);
        float2 w3 = cmulf(w1, w2);

        float2 a = s[i0];
        float2 b = cmulf(s[i1], w1);
        float2 c = cmulf(s[i2], w2);
        float2 d = cmulf(s[i3], w3);

        float2 acp = make_float2(a.x + c.x, a.y + c.y);
        float2 acm = make_float2(a.x - c.x, a.y - c.y);
        float2 bdp = make_float2(b.x + d.x, b.y + d.y);
        float2 bdm = make_float2(b.x - d.x, b.y - d.y);
        float2 ib = inv ? make_float2(-bdm.y, bdm.x) : make_float2(bdm.y, -bdm.x);

        s[i0] = make_float2(acp.x + bdp.x, acp.y + bdp.y);
        s[i1] = make_float2(acm.x + ib.x,  acm.y + ib.y);
        s[i2] = make_float2(acp.x - bdp.x, acp.y - bdp.y);
        s[i3] = make_float2(acm.x - ib.x,  acm.y - ib.y);
        __syncthreads();
    }
}

__global__ __launch_bounds__(256) void fft_attn_kernel(
    const float* __restrict__ Q, const float* __restrict__ Kx,
    const float* __restrict__ V,
    __half* __restrict__ Oh, __half* __restrict__ Om)
{
    __shared__ float2 Z[1024];
    __shared__ float2 A0[1024];
    __shared__ float2 A1[1024];
    __shared__ float2 Tw[256];
    const int row0 = blockIdx.x * 2;
    const int row1 = row0 + 1;
    const int tid = threadIdx.x;
    const float* q0 = Q  + (size_t)row0 * Pd;
    const float* k0 = Kx + (size_t)row0 * Pd;
    const float* q1 = Q  + (size_t)row1 * Pd;
    const float* k1 = Kx + (size_t)row1 * Pd;
    const float* v0 = V  + (size_t)row0 * Pd;
    const float* v1 = V  + (size_t)row1 * Pd;

    {
        float sn, cs;
        __sincosf(-6.283185307179586f * (float)tid / 1024.0f, &sn, &cs);
        Tw[tid] = make_float2(cs, sn);
    }

    const float inv_scale = 1.0f / 32.0f;

    // --- row0: fft(q0 + i k0), Aw0 -> A0 ---
    #pragma unroll
    for (int u = 0; u < 4; u++) {
        int i = tid + u * 256;
        Z[rev4(i)] = make_float2(q0[i], k0[i]);
    }
    __syncthreads();
    fft1024_r4(Z, Tw, tid, false);
    #pragma unroll
    for (int u = 0; u < 4; u++) {
        int i = tid + u * 256;
        float2 zj = Z[i];
        float2 zn = Z[(1024 - i) & 1023];
        float Qx = 0.5f * (zj.x + zn.x), Qy = 0.5f * (zj.y - zn.y);
        float Kxr = 0.5f * (zj.y + zn.y), Kyr = -0.5f * (zj.x - zn.x);
        A0[i] = make_float2((Kxr * Qx + Kyr * Qy) * inv_scale,
                            (Kyr * Qx - Kxr * Qy) * inv_scale);
    }
    __syncthreads();

    // --- row1: fft(q1 + i k1), Aw1 -> A1 ---
    #pragma unroll
    for (int u = 0; u < 4; u++) {
        int i = tid + u * 256;
        Z[rev4(i)] = make_float2(q1[i], k1[i]);
    }
    __syncthreads();
    fft1024_r4(Z, Tw, tid, false);
    #pragma unroll
    for (int u = 0; u < 4; u++) {
        int i = tid + u * 256;
        float2 zj = Z[i];
        float2 zn = Z[(1024 - i) & 1023];
        float Qx = 0.5f * (zj.x + zn.x), Qy = 0.5f * (zj.y - zn.y);
        float Kxr = 0.5f * (zj.y + zn.y), Kyr = -0.5f * (zj.x - zn.x);
        A1[i] = make_float2((Kxr * Qx + Kyr * Qy) * inv_scale,
                            (Kyr * Qx - Kxr * Qy) * inv_scale);
    }
    __syncthreads();

    // --- fft(v0 + i v1), unpack, W = Aw * V ---
    #pragma unroll
    for (int u = 0; u < 4; u++) {
        int i = tid + u * 256;
        Z[rev4(i)] = make_float2(v0[i], v1[i]);
    }
    __syncthreads();
    fft1024_r4(Z, Tw, tid, false);
    #pragma unroll
    for (int u = 0; u < 4; u++) {
        int i = tid + u * 256;
        float2 zj = Z[i];
        float2 zn = Z[(1024 - i) & 1023];
        float2 V0 = make_float2(0.5f * (zj.x + zn.x), 0.5f * (zj.y - zn.y));
        float2 V1 = make_float2(0.5f * (zj.y + zn.y), -0.5f * (zj.x - zn.x));
        A0[i] = cmulf(A0[i], V0);
        A1[i] = cmulf(A1[i], V1);
    }
    __syncthreads();

    // --- symmetrize: S(k) = 0.5*(W(k)+conj(W(-k))); pack S0 + i S1, ifft ---
    #pragma unroll
    for (int u = 0; u < 4; u++) {
        int i = tid + u * 256;
        int ni = (1024 - i) & 1023;
        float2 w0 = A0[i], w0n = A0[ni];
        float2 w1 = A1[i], w1n = A1[ni];
        float2 S0 = make_float2(0.5f * (w0.x + w0n.x), 0.5f * (w0.y - w0n.y));
        float2 S1 = make_float2(0.5f * (w1.x + w1n.x), 0.5f * (w1.y - w1n.y));
        Z[rev4(i)] = make_float2(S0.x - S1.y, S0.y + S1.x);
    }
    __syncthreads();
    fft1024_r4(Z, Tw, tid, true);

    __half* oh0 = Oh + (size_t)row0 * Pd;
    __half* om0 = Om + (size_t)row0 * Pd;
    __half* oh1 = Oh + (size_t)row1 * Pd;
    __half* om1 = Om + (size_t)row1 * Pd;
    const float invN = 1.0f / 1024.0f;
    #pragma unroll
    for (int u = 0; u < 4; u++) {
        int i = tid + u * 256;
        float s0 = Z[i].x * invN;
        float s1 = Z[i].y * invN;
        __half h0, m0, h1, m1;
        split2h(s0, h0, m0);
        split2h(s1, h1, m1);
        oh0[i] = h0; om0[i] = m0;
        oh1[i] = h1; om1[i] = m1;
    }
}

// ---------------- launch ----------------
extern "C" void kernel_launch(void* const* d_in, const int* in_sizes, int n_in,
                              void* d_out, int out_size) {
    (void)in_sizes; (void)n_in; (void)out_size;
    const float* x      = (const float*)d_in[0];
    const float* conv_w = (const float*)d_in[1];
    const float* conv_b = (const float*)d_in[2];
    const float* wq     = (const float*)d_in[3];
    const float* bq     = (const float*)d_in[4];
    const float* wk     = (const float*)d_in[5];
    const float* bk     = (const float*)d_in[6];
    const float* wv     = (const float*)d_in[7];
    const float* bv     = (const float*)d_in[8];
    const float* wo     = (const float*)d_in[9];
    const float* bo     = (const float*)d_in[10];
    float* out = (float*)d_out;

    float *xb, *qkv, *bqkv, *wavg, *bavg;
    __half *ch, *cm, *ph, *pm, *wqkvh, *woh;
    cudaGetSymbolAddress((void**)&xb,    g_x);
    cudaGetSymbolAddress((void**)&ch,    g_ch);
    cudaGetSymbolAddress((void**)&cm,    g_cm);
    cudaGetSymbolAddress((void**)&qkv,   g_qkv);
    cudaGetSymbolAddress((void**)&ph,    g_ph);
    cudaGetSymbolAddress((void**)&pm,    g_pm);
    cudaGetSymbolAddress((void**)&wqkvh, g_wqkv);
    cudaGetSymbolAddress((void**)&woh,   g_wo);
    cudaGetSymbolAddress((void**)&bqkv,  g_bqkv);
    cudaGetSymbolAddress((void**)&wavg,  g_wavg);
    cudaGetSymbolAddress((void**)&bavg,  g_bavg);

    cudaFuncSetAttribute(gemm_qkv_kernel,
                         cudaFuncAttributeMaxDynamicSharedMemorySize, QGEMM_SMEM);
    cudaFuncSetAttribute(gemm_wo_kernel,
                         cudaFuncAttributeMaxDynamicSharedMemorySize, GEMM_SMEM);

    const size_t LPW = (size_t)Ld * Pd * Wd;   // 4M elements

    avg_conv_kernel<<<1, 64>>>(conv_w, conv_b, wavg, bavg);

    cvt16_all_kernel<<<2048, 256>>>(wq, wk, wv, wo, wqkvh, woh, (int)(LPW / 8));

    cudaMemcpyAsync(bqkv,               bq, Ld * Pd * 4, cudaMemcpyDeviceToDevice);
    cudaMemcpyAsync(bqkv + Ld * Pd,     bk, Ld * Pd * 4, cudaMemcpyDeviceToDevice);
    cudaMemcpyAsync(bqkv + 2 * Ld * Pd, bv, Ld * Pd * 4, cudaMemcpyDeviceToDevice);

    const size_t RP = (size_t)ROWS * Pd;

    for (int l = 0; l < Ld; l++) {
        const float* xin = (l == 0) ? x : xb;
        float* xout = (l == Ld - 1) ? out : xb;

        conv_row_kernel<<<ROWS, 256>>>(xin, ch, cm, wavg + l * Kc, bavg + l);

        dim3 gq(Pd / 64, ROWS / 128);         // (16, 32)
        gemm_qkv_kernel<<<gq, 256, QGEMM_SMEM>>>(
            ch, cm,
            wqkvh + (size_t)l * Pd * Wd,
            bqkv + (size_t)l * Pd, qkv, LPW);

        fft_attn_kernel<<<ROWS / 2, 256>>>(qkv, qkv + RP, qkv + 2 * RP, ph, pm);

        dim3 go(Wd / 128, ROWS / 128);        // (16, 32)
        gemm_wo_kernel<<<go, 256, GEMM_SMEM>>>(
            ph, pm,
            woh + (size_t)l * Wd * Pd,
            bo + (size_t)l * Wd, xout,
            Pd, Wd);
    }
}

// round 14
// speedup vs baseline: 1.1085x; 1.1085x over previous
#include <cuda_runtime.h>
#include <cuda_fp16.h>
#include <cstdint>

#define BSZ 32
#define CNT 128
#define Wd  2048
#define Pd  1024
#define Ed  8
#define Kc  25
#define Ld  2
#define ROWS (BSZ*CNT)   // 4096

// ---------------- scratch ----------------
__device__ float  g_x[ROWS*Wd];
__device__ __half g_ch[ROWS*Wd];
__device__ __half g_cm[ROWS*Wd];
__device__ float  g_qkv[3*ROWS*Pd];
__device__ __half g_ph[ROWS*Pd];
__device__ __half g_pm[ROWS*Pd];
__device__ __half g_wqkv[3*Ld*Pd*Wd];
__device__ __half g_wo[Ld*Wd*Pd];
__device__ float  g_bqkv[3*Ld*Pd];
__device__ float  g_wavg[Ld*Kc];
__device__ float  g_bavg[Ld];

// ---------------- helpers ----------------
__device__ __forceinline__ uint32_t smem_u32(const void* p) {
    uint32_t a;
    asm("{ .reg .u64 t; cvta.to.shared.u64 t, %1; cvt.u32.u64 %0, t; }" : "=r"(a) : "l"(p));
    return a;
}
__device__ __forceinline__ void cp16(uint32_t dst, const void* src) {
    asm volatile("cp.async.cg.shared.global [%0], [%1], 16;" :: "r"(dst), "l"(src));
}
__device__ __forceinline__ void split2h(float x, __half& h, __half& m) {
    h = __float2half(x);
    m = __float2half(x - __half2float(h));
}
__device__ __forceinline__ uint32_t pack2h(__half a, __half b) {
    return (uint32_t)__half_as_ushort(a) | ((uint32_t)__half_as_ushort(b) << 16);
}
__device__ __forceinline__ float2 cmulf(float2 a, float2 b) {
    return make_float2(a.x * b.x - a.y * b.y, a.x * b.y + a.y * b.x);
}

// ---------------- weight convert fp32 -> fp16 (all 4 matrices, one launch) ----------------
__global__ void cvt16_all_kernel(const float* __restrict__ wq, const float* __restrict__ wk,
                                 const float* __restrict__ wv, const float* __restrict__ wo,
                                 __half* __restrict__ wqkv, __half* __restrict__ wod, int n8) {
    int i = blockIdx.x * blockDim.x + threadIdx.x;
    int stride = gridDim.x * blockDim.x;
    for (; i < 4 * n8; i += stride) {
        int sel = i / n8, j = i - sel * n8;
        const float* src = (sel == 0) ? wq : (sel == 1) ? wk : (sel == 2) ? wv : wo;
        __half* dst = (sel < 3) ? (wqkv + (size_t)sel * n8 * 8) : wod;
        float4 v0 = ((const float4*)src)[2 * j];
        float4 v1 = ((const float4*)src)[2 * j + 1];
        uint4 u;
        u.x = pack2h(__float2half(v0.x), __float2half(v0.y));
        u.y = pack2h(__float2half(v0.z), __float2half(v0.w));
        u.z = pack2h(__float2half(v1.x), __float2half(v1.y));
        u.w = pack2h(__float2half(v1.z), __float2half(v1.w));
        ((uint4*)dst)[j] = u;
    }
}

// ---------------- avg conv weights ----------------
__global__ void avg_conv_kernel(const float* __restrict__ cw, const float* __restrict__ cb,
                                float* __restrict__ wavg, float* __restrict__ bavg) {
    int idx = threadIdx.x;
    if (idx < Ld * Kc) {
        int l = idx / Kc, kk = idx % Kc;
        float s = 0.f;
        #pragma unroll
        for (int e = 0; e < Ed; e++) s += cw[(l * Ed + e) * Kc + kk];
        wavg[idx] = s * (1.0f / Ed);
    }
    if (idx < Ld) {
        float s = 0.f;
        #pragma unroll
        for (int e = 0; e < Ed; e++) s += cb[idx * Ed + e];
        bavg[idx] = s * (1.0f / Ed);
    }
}

// ---------------- 1D conv, writes fp16 h/m ----------------
__global__ __launch_bounds__(256) void conv_row_kernel(
    const float* __restrict__ X, __half* __restrict__ Yh, __half* __restrict__ Ym,
    const float* __restrict__ wavg, const float* __restrict__ bavg)
{
    __shared__ float sx[Wd + Kc - 1];
    __shared__ float wsh[Kc];
    const int row = blockIdx.x;
    const int tid = threadIdx.x;
    const float* xr = X + (size_t)row * Wd;

    for (int i = tid; i < Wd + Kc - 1; i += 256) {
        int src = i - (Kc / 2);
        sx[i] = (src >= 0 && src < Wd) ? xr[src] : 0.0f;
    }
    if (tid < Kc) wsh[tid] = wavg[tid];
    __syncthreads();

    const float b = bavg[0];
    __half* yh = Yh + (size_t)row * Wd;
    __half* ym = Ym + (size_t)row * Wd;
    for (int h = tid; h < Wd; h += 256) {
        float s = b;
        #pragma unroll
        for (int k = 0; k < Kc; k++) s += sx[h + k] * wsh[k];
        __half sh, sm_;
        split2h(s, sh, sm_);
        yh[h] = sh; ym[h] = sm_;
    }
}

// ---------------- fp16x2 mma.sync GEMM, 32x64 warp tile (round-12 proven) ----------------
#define MMA16(cc, aa, bb) \
    asm volatile("mma.sync.aligned.m16n8k16.row.col.f32.f16.f16.f32 " \
        "{%0,%1,%2,%3},{%4,%5,%6,%7},{%8,%9},{%0,%1,%2,%3};" \
        : "+f"((cc)[0]), "+f"((cc)[1]), "+f"((cc)[2]), "+f"((cc)[3]) \
        : "r"((aa)[0]), "r"((aa)[1]), "r"((aa)[2]), "r"((aa)[3]), \
          "r"((bb)[0]), "r"((bb)[1]))

#define LDMX4(r0, r1, r2, r3, a) \
    asm volatile("ldmatrix.sync.aligned.m8n8.x4.shared.b16 {%0,%1,%2,%3}, [%4];" \
        : "=r"(r0), "=r"(r1), "=r"(r2), "=r"(r3) : "r"(a))

#define BK 32
#define TILE_W 2048            // 128 rows x 16 words (32 fp16), swizzled
#define STAGE_W (3*TILE_W)     // Ah, Am, W = 6144 words = 24KB
#define NSTAGE 3
#define GEMM_SMEM (NSTAGE*STAGE_W*4)   // 73728 bytes

__global__ __launch_bounds__(256, 2) void gemm_mma_kernel(
    const __half* __restrict__ Ah, const __half* __restrict__ Am,
    const __half* __restrict__ Bw,
    const float* __restrict__ bias, float* __restrict__ C,
    int Kd, int N, size_t szB, size_t szBias, size_t szC)
{
    extern __shared__ uint32_t sm[];
    const uint32_t sbase = smem_u32(sm);
    const int z = blockIdx.z;
    Bw   += (size_t)z * szB;
    bias += (size_t)z * szBias;
    C    += (size_t)z * szC;

    const int tid = threadIdx.x;
    const int wid = tid >> 5, lane = tid & 31;
    const int g = lane >> 2, t = lane & 3;
    const int wm = (wid >> 1) * 32;
    const int wn = (wid & 1) * 64;
    const int bm = blockIdx.y * 128, bn = blockIdx.x * 128;
    const int stA = wid & 1;

    const int lr = lane & 7;
    const int ls = lane >> 3;
    uint32_t Abase[2], Bbase[2];
    #pragma unroll
    for (int st = 0; st < 2; st++) {
        int arow = wm + lr + (ls & 1) * 8;
        int awc2 = st * 2 + (ls >> 1);
        Abase[st] = (uint32_t)(arow * 16 + ((awc2 ^ ((arow >> 1) & 3)) << 2)) * 4;
        int brow = wn + (ls >> 1) * 8 + lr;
        int bwc2 = st * 2 + (ls & 1);
        Bbase[st] = (uint32_t)(brow * 16 + ((bwc2 ^ ((brow >> 1) & 3)) << 2)) * 4;
    }

    const int r0 = tid >> 2, c0 = tid & 3;
    const int r1 = r0 + 64;
    const uint32_t d0 = (uint32_t)(r0 * 16 + ((c0 ^ ((r0 >> 1) & 3)) << 2)) * 4;
    const uint32_t d1 = (uint32_t)(r1 * 16 + ((c0 ^ ((r1 >> 1) & 3)) << 2)) * 4;

    const __half* a0h = Ah + (size_t)(bm + r0) * Kd + c0 * 8;
    const __half* a0m = Am + (size_t)(bm + r0) * Kd + c0 * 8;
    const __half* a1h = Ah + (size_t)(bm + r1) * Kd + c0 * 8;
    const __half* a1m = Am + (size_t)(bm + r1) * Kd + c0 * 8;
    const __half* b0w = Bw + (size_t)(bn + r0) * Kd + c0 * 8;
    const __half* b1w = Bw + (size_t)(bn + r1) * Kd + c0 * 8;

    float acc[2][8][4];
    #pragma unroll
    for (int mt = 0; mt < 2; mt++)
        #pragma unroll
        for (int nt = 0; nt < 8; nt++)
            #pragma unroll
            for (int e = 0; e < 4; e++) acc[mt][nt][e] = 0.0f;

    const int NC = Kd / BK;

    #define ISSUE(s, kpos) do { \
        uint32_t _sb = sbase + (uint32_t)(s) * (STAGE_W * 4); \
        cp16(_sb + d0,                   a0h + (kpos)); \
        cp16(_sb + d1,                   a1h + (kpos)); \
        cp16(_sb + TILE_W * 4 + d0,      a0m + (kpos)); \
        cp16(_sb + TILE_W * 4 + d1,      a1m + (kpos)); \
        cp16(_sb + 2 * TILE_W * 4 + d0,  b0w + (kpos)); \
        cp16(_sb + 2 * TILE_W * 4 + d1,  b1w + (kpos)); \
        asm volatile("cp.async.commit_group;" ::: "memory"); \
    } while (0)

    ISSUE(0, 0);
    ISSUE(1, BK);

    for (int i = 0; i < NC; i++) {
        if (i + 1 < NC) asm volatile("cp.async.wait_group 1;" ::: "memory");
        else            asm volatile("cp.async.wait_group 0;" ::: "memory");
        __syncthreads();
        if (i + 2 < NC) {
            int s = i + 2; s = s - (s / 3) * 3;
            ISSUE(s, (i + 2) * BK);
        }

        int bsel = i - (i / 3) * 3;
        const uint32_t sAh = sbase + (uint32_t)bsel * (STAGE_W * 4);
        const uint32_t sAm = sAh + TILE_W * 4;
        const uint32_t sBw = sAm + TILE_W * 4;

        #pragma unroll
        for (int s = 0; s < 2; s++) {
            const int st = s ^ stA;
            const uint32_t ab = Abase[st];
            const uint32_t bb = Bbase[st];

            uint32_t bw[8][2];
            LDMX4(bw[0][0], bw[0][1], bw[1][0], bw[1][1], sBw + bb);
            LDMX4(bw[2][0], bw[2][1], bw[3][0], bw[3][1], sBw + bb + 1024);
            LDMX4(bw[4][0], bw[4][1], bw[5][0], bw[5][1], sBw + bb + 2048);
            LDMX4(bw[6][0], bw[6][1], bw[7][0], bw[7][1], sBw + bb + 3072);

            #pragma unroll
            for (int mt = 0; mt < 2; mt++) {
                uint32_t ah[4], am_[4];
                uint32_t ao = ab + (uint32_t)mt * 1024;
                LDMX4(ah[0], ah[1], ah[2], ah[3], sAh + ao);
                LDMX4(am_[0], am_[1], am_[2], am_[3], sAm + ao);
                #pragma unroll
                for (int nt = 0; nt < 8; nt++) {
                    MMA16(acc[mt][nt], ah,  bw[nt]);
                    MMA16(acc[mt][nt], am_, bw[nt]);
                }
            }
        }
        __syncthreads();
    }
    #undef ISSUE

    #pragma unroll
    for (int mt = 0; mt < 2; mt++) {
        #pragma unroll
        for (int nt = 0; nt < 8; nt++) {
            int col = bn + wn + nt * 8 + 2 * t;
            float b0 = __ldg(&bias[col]);
            float b1 = __ldg(&bias[col + 1]);
            float* p0 = C + (size_t)(bm + wm + mt * 16 + g) * N + col;
            float2 o0 = make_float2(acc[mt][nt][0] + b0, acc[mt][nt][1] + b1);
            float2 o1 = make_float2(acc[mt][nt][2] + b0, acc[mt][nt][3] + b1);
            *(float2*)p0 = o0;
            *(float2*)(p0 + 8 * N) = o1;
        }
    }
}

// ---------------- radix-4 FFT attention, 2 rows per block ----------------
__device__ __forceinline__ int rev4(int v) {
    return ((v & 3) << 8) | (((v >> 2) & 3) << 6) | (((v >> 4) & 3) << 4)
         | (((v >> 6) & 3) << 2) | ((v >> 8) & 3);
}

__device__ __forceinline__ void fft1024_r4(float2* s, const float2* Tw, int tid, bool inv) {
    #pragma unroll
    for (int stage = 0; stage < 5; ++stage) {
        const int q = 1 << (2 * stage);
        const int j = tid & (q - 1);
        const int grp = tid >> (2 * stage);
        const int i0 = grp * (q << 2) + j;
        const int i1 = i0 + q, i2 = i1 + q, i3 = i2 + q;

        float2 w1 = Tw[j << (8 - 2 * stage)];
        if (inv) w1.y = -w1.y;
        float2 w2 = cmulf(w1, w1);
        float2 w3 = cmulf(w1, w2);

        float2 a = s[i0];
        float2 b = cmulf(s[i1], w1);
        float2 c = cmulf(s[i2], w2);
        float2 d = cmulf(s[i3], w3);

        float2 acp = make_float2(a.x + c.x, a.y + c.y);
        float2 acm = make_float2(a.x - c.x, a.y - c.y);
        float2 bdp = make_float2(b.x + d.x, b.y + d.y);
        float2 bdm = make_float2(b.x - d.x, b.y - d.y);
        float2 ib = inv ? make_float2(-bdm.y, bdm.x) : make_float2(bdm.y, -bdm.x);

        s[i0] = make_float2(acp.x + bdp.x, acp.y + bdp.y);
        s[i1] = make_float2(acm.x + ib.x,  acm.y + ib.y);
        s[i2] = make_float2(acp.x - bdp.x, acp.y - bdp.y);
        s[i3] = make_float2(acm.x - ib.x,  acm.y - ib.y);
        __syncthreads();
    }
}

__global__ __launch_bounds__(256) void fft_attn_kernel(
    const float* __restrict__ Q, const float* __restrict__ Kx,
    const float* __restrict__ V,
    __half* __restrict__ Oh, __half* __restrict__ Om)
{
    __shared__ float2 Z[1024];
    __shared__ float2 A0[1024];
    __shared__ float2 A1[1024];
    __shared__ float2 Tw[256];
    const int row0 = blockIdx.x * 2;
    const int row1 = row0 + 1;
    const int tid = threadIdx.x;
    const float* q0 = Q  + (size_t)row0 * Pd;
    const float* k0 = Kx + (size_t)row0 * Pd;
    const float* q1 = Q  + (size_t)row1 * Pd;
    const float* k1 = Kx + (size_t)row1 * Pd;
    const float* v0 = V  + (size_t)row0 * Pd;
    const float* v1 = V  + (size_t)row1 * Pd;

    {
        float sn, cs;
        __sincosf(-6.283185307179586f * (float)tid / 1024.0f, &sn, &cs);
        Tw[tid] = make_float2(cs, sn);
    }

    const float inv_scale = 1.0f / 32.0f;

    #pragma unroll
    for (int u = 0; u < 4; u++) {
        int i = tid + u * 256;
        Z[rev4(i)] = make_float2(q0[i], k0[i]);
    }
    __syncthreads();
    fft1024_r4(Z, Tw, tid, false);
    #pragma unroll
    for (int u = 0; u < 4; u++) {
        int i = tid + u * 256;
        float2 zj = Z[i];
        float2 zn = Z[(1024 - i) & 1023];
        float Qx = 0.5f * (zj.x + zn.x), Qy = 0.5f * (zj.y - zn.y);
        float Kxr = 0.5f * (zj.y + zn.y), Kyr = -0.5f * (zj.x - zn.x);
        A0[i] = make_float2((Kxr * Qx + Kyr * Qy) * inv_scale,
                            (Kyr * Qx - Kxr * Qy) * inv_scale);
    }
    __syncthreads();

    #pragma unroll
    for (int u = 0; u < 4; u++) {
        int i = tid + u * 256;
        Z[rev4(i)] = make_float2(q1[i], k1[i]);
    }
    __syncthreads();
    fft1024_r4(Z, Tw, tid, false);
    #pragma unroll
    for (int u = 0; u < 4; u++) {
        int i = tid + u * 256;
        float2 zj = Z[i];
        float2 zn = Z[(1024 - i) & 1023];
        float Qx = 0.5f * (zj.x + zn.x), Qy = 0.5f * (zj.y - zn.y);
        float Kxr = 0.5f * (zj.y + zn.y), Kyr = -0.5f * (zj.x - zn.x);
        A1[i] = make_float2((Kxr * Qx + Kyr * Qy) * inv_scale,
                            (Kyr * Qx - Kxr * Qy) * inv_scale);
    }
    __syncthreads();

    #pragma unroll
    for (int u = 0; u < 4; u++) {
        int i = tid + u * 256;
        Z[rev4(i)] = make_float2(v0[i], v1[i]);
    }
    __syncthreads();
    fft1024_r4(Z, Tw, tid, false);
    #pragma unroll
    for (int u = 0; u < 4; u++) {
        int i = tid + u * 256;
        float2 zj = Z[i];
        float2 zn = Z[(1024 - i) & 1023];
        float2 V0 = make_float2(0.5f * (zj.x + zn.x), 0.5f * (zj.y - zn.y));
        float2 V1 = make_float2(0.5f * (zj.y + zn.y), -0.5f * (zj.x - zn.x));
        A0[i] = cmulf(A0[i], V0);
        A1[i] = cmulf(A1[i], V1);
    }
    __syncthreads();

    #pragma unroll
    for (int u = 0; u < 4; u++) {
        int i = tid + u * 256;
        int ni = (1024 - i) & 1023;
        float2 w0 = A0[i], w0n = A0[ni];
        float2 w1 = A1[i], w1n = A1[ni];
        float2 S0 = make_float2(0.5f * (w0.x + w0n.x), 0.5f * (w0.y - w0n.y));
        float2 S1 = make_float2(0.5f * (w1.x + w1n.x), 0.5f * (w1.y - w1n.y));
        Z[rev4(i)] = make_float2(S0.x - S1.y, S0.y + S1.x);
    }
    __syncthreads();
    fft1024_r4(Z, Tw, tid, true);

    __half* oh0 = Oh + (size_t)row0 * Pd;
    __half* om0 = Om + (size_t)row0 * Pd;
    __half* oh1 = Oh + (size_t)row1 * Pd;
    __half* om1 = Om + (size_t)row1 * Pd;
    const float invN = 1.0f / 1024.0f;
    #pragma unroll
    for (int u = 0; u < 4; u++) {
        int i = tid + u * 256;
        float s0 = Z[i].x * invN;
        float s1 = Z[i].y * invN;
        __half h0, m0, h1, m1;
        split2h(s0, h0, m0);
        split2h(s1, h1, m1);
        oh0[i] = h0; om0[i] = m0;
        oh1[i] = h1; om1[i] = m1;
    }
}

// ---------------- launch ----------------
extern "C" void kernel_launch(void* const* d_in, const int* in_sizes, int n_in,
                              void* d_out, int out_size) {
    (void)in_sizes; (void)n_in; (void)out_size;
    const float* x      = (const float*)d_in[0];
    const float* conv_w = (const float*)d_in[1];
    const float* conv_b = (const float*)d_in[2];
    const float* wq     = (const float*)d_in[3];
    const float* bq     = (const float*)d_in[4];
    const float* wk     = (const float*)d_in[5];
    const float* bk     = (const float*)d_in[6];
    const float* wv     = (const float*)d_in[7];
    const float* bv     = (const float*)d_in[8];
    const float* wo     = (const float*)d_in[9];
    const float* bo     = (const float*)d_in[10];
    float* out = (float*)d_out;

    float *xb, *qkv, *bqkv, *wavg, *bavg;
    __half *ch, *cm, *ph, *pm, *wqkvh, *woh;
    cudaGetSymbolAddress((void**)&xb,    g_x);
    cudaGetSymbolAddress((void**)&ch,    g_ch);
    cudaGetSymbolAddress((void**)&cm,    g_cm);
    cudaGetSymbolAddress((void**)&qkv,   g_qkv);
    cudaGetSymbolAddress((void**)&ph,    g_ph);
    cudaGetSymbolAddress((void**)&pm,    g_pm);
    cudaGetSymbolAddress((void**)&wqkvh, g_wqkv);
    cudaGetSymbolAddress((void**)&woh,   g_wo);
    cudaGetSymbolAddress((void**)&bqkv,  g_bqkv);
    cudaGetSymbolAddress((void**)&wavg,  g_wavg);
    cudaGetSymbolAddress((void**)&bavg,  g_bavg);

    cudaFuncSetAttribute(gemm_mma_kernel,
                         cudaFuncAttributeMaxDynamicSharedMemorySize, GEMM_SMEM);

    const size_t LPW = (size_t)Ld * Pd * Wd;   // 4M elements

    avg_conv_kernel<<<1, 64>>>(conv_w, conv_b, wavg, bavg);

    cvt16_all_kernel<<<2048, 256>>>(wq, wk, wv, wo, wqkvh, woh, (int)(LPW / 8));

    cudaMemcpyAsync(bqkv,               bq, Ld * Pd * 4, cudaMemcpyDeviceToDevice);
    cudaMemcpyAsync(bqkv + Ld * Pd,     bk, Ld * Pd * 4, cudaMemcpyDeviceToDevice);
    cudaMemcpyAsync(bqkv + 2 * Ld * Pd, bv, Ld * Pd * 4, cudaMemcpyDeviceToDevice);

    const size_t RP = (size_t)ROWS * Pd;

    for (int l = 0; l < Ld; l++) {
        const float* xin = (l == 0) ? x : xb;
        float* xout = (l == Ld - 1) ? out : xb;

        conv_row_kernel<<<ROWS, 256>>>(xin, ch, cm, wavg + l * Kc, bavg + l);

        dim3 gq(Pd / 128, ROWS / 128, 3);     // (8, 32, 3)
        gemm_mma_kernel<<<gq, 256, GEMM_SMEM>>>(
            ch, cm,
            wqkvh + (size_t)l * Pd * Wd,
            bqkv + (size_t)l * Pd, qkv,
            Wd, Pd, LPW, (size_t)Ld * Pd, RP);

        fft_attn_kernel<<<ROWS / 2, 256>>>(qkv, qkv + RP, qkv + 2 * RP, ph, pm);

        dim3 go(Wd / 128, ROWS / 128, 1);     // (16, 32, 1)
        gemm_mma_kernel<<<go, 256, GEMM_SMEM>>>(
            ph, pm,
            woh + (size_t)l * Wd * Pd,
            bo + (size_t)l * Wd, xout,
            Pd, Wd, 0, 0, 0);
    }
}

// round 15
// speedup vs baseline: 1.1784x; 1.0631x over previous
#include <cuda_runtime.h>
#include <cuda_fp16.h>
#include <cstdint>

#define BSZ 32
#define CNT 128
#define Wd  2048
#define Pd  1024
#define Ed  8
#define Kc  25
#define Ld  2
#define ROWS (BSZ*CNT)   // 4096

// ---------------- scratch ----------------
__device__ float  g_x[ROWS*Wd];
__device__ __half g_ch[ROWS*Wd];
__device__ __half g_cm[ROWS*Wd];
__device__ float  g_qkv[3*ROWS*Pd];
__device__ __half g_ph[ROWS*Pd];
__device__ __half g_pm[ROWS*Pd];
__device__ __half g_wqkv[3*Ld*Pd*Wd];
__device__ __half g_wo[Ld*Wd*Pd];
__device__ float  g_bqkv[3*Ld*Pd];
__device__ float  g_wavg[Ld*Kc];
__device__ float  g_bavg[Ld];

// ---------------- helpers ----------------
__device__ __forceinline__ uint32_t smem_u32(const void* p) {
    uint32_t a;
    asm("{ .reg .u64 t; cvta.to.shared.u64 t, %1; cvt.u32.u64 %0, t; }" : "=r"(a) : "l"(p));
    return a;
}
__device__ __forceinline__ void cp16(uint32_t dst, const void* src) {
    asm volatile("cp.async.cg.shared.global [%0], [%1], 16;" :: "r"(dst), "l"(src));
}
__device__ __forceinline__ void split2h(float x, __half& h, __half& m) {
    h = __float2half(x);
    m = __float2half(x - __half2float(h));
}
__device__ __forceinline__ uint32_t pack2h(__half a, __half b) {
    return (uint32_t)__half_as_ushort(a) | ((uint32_t)__half_as_ushort(b) << 16);
}
__device__ __forceinline__ float2 cmulf(float2 a, float2 b) {
    return make_float2(a.x * b.x - a.y * b.y, a.x * b.y + a.y * b.x);
}

// ---------------- weight convert fp32 -> fp16 (all 4 matrices, one launch) ----------------
__global__ void cvt16_all_kernel(const float* __restrict__ wq, const float* __restrict__ wk,
                                 const float* __restrict__ wv, const float* __restrict__ wo,
                                 __half* __restrict__ wqkv, __half* __restrict__ wod, int n8) {
    int i = blockIdx.x * blockDim.x + threadIdx.x;
    int stride = gridDim.x * blockDim.x;
    for (; i < 4 * n8; i += stride) {
        int sel = i / n8, j = i - sel * n8;
        const float* src = (sel == 0) ? wq : (sel == 1) ? wk : (sel == 2) ? wv : wo;
        __half* dst = (sel < 3) ? (wqkv + (size_t)sel * n8 * 8) : wod;
        float4 v0 = ((const float4*)src)[2 * j];
        float4 v1 = ((const float4*)src)[2 * j + 1];
        uint4 u;
        u.x = pack2h(__float2half(v0.x), __float2half(v0.y));
        u.y = pack2h(__float2half(v0.z), __float2half(v0.w));
        u.z = pack2h(__float2half(v1.x), __float2half(v1.y));
        u.w = pack2h(__float2half(v1.z), __float2half(v1.w));
        ((uint4*)dst)[j] = u;
    }
}

// ---------------- avg conv weights ----------------
__global__ void avg_conv_kernel(const float* __restrict__ cw, const float* __restrict__ cb,
                                float* __restrict__ wavg, float* __restrict__ bavg) {
    int idx = threadIdx.x;
    if (idx < Ld * Kc) {
        int l = idx / Kc, kk = idx % Kc;
        float s = 0.f;
        #pragma unroll
        for (int e = 0; e < Ed; e++) s += cw[(l * Ed + e) * Kc + kk];
        wavg[idx] = s * (1.0f / Ed);
    }
    if (idx < Ld) {
        float s = 0.f;
        #pragma unroll
        for (int e = 0; e < Ed; e++) s += cb[idx * Ed + e];
        bavg[idx] = s * (1.0f / Ed);
    }
}

// ---------------- 1D conv, writes fp16 h/m ----------------
__global__ __launch_bounds__(256) void conv_row_kernel(
    const float* __restrict__ X, __half* __restrict__ Yh, __half* __restrict__ Ym,
    const float* __restrict__ wavg, const float* __restrict__ bavg)
{
    __shared__ float sx[Wd + Kc - 1];
    __shared__ float wsh[Kc];
    const int row = blockIdx.x;
    const int tid = threadIdx.x;
    const float* xr = X + (size_t)row * Wd;

    for (int i = tid; i < Wd + Kc - 1; i += 256) {
        int src = i - (Kc / 2);
        sx[i] = (src >= 0 && src < Wd) ? xr[src] : 0.0f;
    }
    if (tid < Kc) wsh[tid] = wavg[tid];
    __syncthreads();

    const float b = bavg[0];
    __half* yh = Yh + (size_t)row * Wd;
    __half* ym = Ym + (size_t)row * Wd;
    for (int h = tid; h < Wd; h += 256) {
        float s = b;
        #pragma unroll
        for (int k = 0; k < Kc; k++) s += sx[h + k] * wsh[k];
        __half sh, sm_;
        split2h(s, sh, sm_);
        yh[h] = sh; ym[h] = sm_;
    }
}

// ---------------- fp16x2 mma.sync GEMM, BK=64, 2-stage ----------------
#define MMA16(cc, aa, bb) \
    asm volatile("mma.sync.aligned.m16n8k16.row.col.f32.f16.f16.f32 " \
        "{%0,%1,%2,%3},{%4,%5,%6,%7},{%8,%9},{%0,%1,%2,%3};" \
        : "+f"((cc)[0]), "+f"((cc)[1]), "+f"((cc)[2]), "+f"((cc)[3]) \
        : "r"((aa)[0]), "r"((aa)[1]), "r"((aa)[2]), "r"((aa)[3]), \
          "r"((bb)[0]), "r"((bb)[1]))

#define LDMX4(r0, r1, r2, r3, a) \
    asm volatile("ldmatrix.sync.aligned.m8n8.x4.shared.b16 {%0,%1,%2,%3}, [%4];" \
        : "=r"(r0), "=r"(r1), "=r"(r2), "=r"(r3) : "r"(a))

#define BK 64
#define TILE_B 16384           // 128 rows x 128 bytes (64 fp16), swizzled
#define STAGE_B (3*TILE_B)     // Ah, Am, W = 48KB
#define GEMM_SMEM (2*STAGE_B)  // 98304 bytes

__global__ __launch_bounds__(256, 2) void gemm_mma_kernel(
    const __half* __restrict__ Ah, const __half* __restrict__ Am,
    const __half* __restrict__ Bw,
    const float* __restrict__ bias, float* __restrict__ C,
    int Kd, int N, size_t szB, size_t szBias, size_t szC)
{
    extern __shared__ uint32_t sm[];
    const uint32_t sbase = smem_u32(sm);
    const int z = blockIdx.z;
    Bw   += (size_t)z * szB;
    bias += (size_t)z * szBias;
    C    += (size_t)z * szC;

    const int tid = threadIdx.x;
    const int wid = tid >> 5, lane = tid & 31;
    const int g = lane >> 2, t = lane & 3;
    const int wm = (wid >> 1) * 32;       // 4 m-groups x 32 rows
    const int wn = (wid & 1) * 64;        // 2 n-groups x 64 cols
    const int bm = blockIdx.y * 128, bn = blockIdx.x * 128;
    const int stA = wid & 1;

    // ---- ldmatrix per-lane byte offsets, 4 k-substeps ----
    // tile layout: row r (0..127), 16B-group gg (0..7); phys group = gg ^ (r & 7)
    const int lr = lane & 7;
    const int ls = lane >> 3;   // 0..3
    uint32_t Abase[4], Bbase[4];
    #pragma unroll
    for (int st = 0; st < 4; st++) {
        int arow = wm + lr + (ls & 1) * 8;
        int agrp = st * 2 + (ls >> 1);
        Abase[st] = (uint32_t)(arow * 128 + ((agrp ^ (arow & 7)) << 4));
        int brow = wn + (ls >> 1) * 8 + lr;
        int bgrp = st * 2 + (ls & 1);
        Bbase[st] = (uint32_t)(brow * 128 + ((bgrp ^ (brow & 7)) << 4));
    }
    // +16 rows => +2048 bytes (row&7 invariant)

    // cp.async mapping: 1024 groups/plane, 4 per thread (j*32 rows apart)
    const int crow = tid >> 3;            // 0..31
    const int cg = tid & 7;               // group 0..7
    const uint32_t sg = (uint32_t)(cg ^ (crow & 7));   // row&7 invariant under +32
    uint32_t cdst[4];
    #pragma unroll
    for (int j = 0; j < 4; j++)
        cdst[j] = (uint32_t)((crow + j * 32) * 128) + (sg << 4);

    const __half* pAh = Ah + (size_t)(bm + crow) * Kd + cg * 8;
    const __half* pAm = Am + (size_t)(bm + crow) * Kd + cg * 8;
    const __half* pBw = Bw + (size_t)(bn + crow) * Kd + cg * 8;
    const size_t rstep = (size_t)32 * Kd;

    float acc[2][8][4];
    #pragma unroll
    for (int mt = 0; mt < 2; mt++)
        #pragma unroll
        for (int nt = 0; nt < 8; nt++)
            #pragma unroll
            for (int e = 0; e < 4; e++) acc[mt][nt][e] = 0.0f;

    const int NC = Kd / BK;

    #define ISSUE(s, kpos) do { \
        uint32_t _sb = sbase + (uint32_t)(s) * STAGE_B; \
        _Pragma("unroll") \
        for (int j = 0; j < 4; j++) { \
            cp16(_sb + cdst[j],              pAh + j * rstep + (kpos)); \
            cp16(_sb + TILE_B + cdst[j],     pAm + j * rstep + (kpos)); \
            cp16(_sb + 2 * TILE_B + cdst[j], pBw + j * rstep + (kpos)); \
        } \
        asm volatile("cp.async.commit_group;" ::: "memory"); \
    } while (0)

    ISSUE(0, 0);

    for (int i = 0; i < NC; i++) {
        if (i + 1 < NC) {
            ISSUE((i + 1) & 1, (i + 1) * BK);
            asm volatile("cp.async.wait_group 1;" ::: "memory");
        } else {
            asm volatile("cp.async.wait_group 0;" ::: "memory");
        }
        __syncthreads();

        const uint32_t sAh = sbase + (uint32_t)(i & 1) * STAGE_B;
        const uint32_t sAm = sAh + TILE_B;
        const uint32_t sBw = sAm + TILE_B;

        #pragma unroll
        for (int s = 0; s < 4; s++) {
            const int st = s ^ stA;
            const uint32_t ab = Abase[st];
            const uint32_t bb = Bbase[st];

            uint32_t bw[8][2];
            LDMX4(bw[0][0], bw[0][1], bw[1][0], bw[1][1], sBw + bb);
            LDMX4(bw[2][0], bw[2][1], bw[3][0], bw[3][1], sBw + bb + 2048);
            LDMX4(bw[4][0], bw[4][1], bw[5][0], bw[5][1], sBw + bb + 4096);
            LDMX4(bw[6][0], bw[6][1], bw[7][0], bw[7][1], sBw + bb + 6144);

            #pragma unroll
            for (int mt = 0; mt < 2; mt++) {
                uint32_t ah[4], am_[4];
                uint32_t ao = ab + (uint32_t)mt * 2048;
                LDMX4(ah[0], ah[1], ah[2], ah[3], sAh + ao);
                LDMX4(am_[0], am_[1], am_[2], am_[3], sAm + ao);
                #pragma unroll
                for (int nt = 0; nt < 8; nt++) {
                    MMA16(acc[mt][nt], ah,  bw[nt]);
                    MMA16(acc[mt][nt], am_, bw[nt]);
                }
            }
        }
        __syncthreads();
    }
    #undef ISSUE

    #pragma unroll
    for (int mt = 0; mt < 2; mt++) {
        #pragma unroll
        for (int nt = 0; nt < 8; nt++) {
            int col = bn + wn + nt * 8 + 2 * t;
            float b0 = __ldg(&bias[col]);
            float b1 = __ldg(&bias[col + 1]);
            float* p0 = C + (size_t)(bm + wm + mt * 16 + g) * N + col;
            float2 o0 = make_float2(acc[mt][nt][0] + b0, acc[mt][nt][1] + b1);
            float2 o1 = make_float2(acc[mt][nt][2] + b0, acc[mt][nt][3] + b1);
            *(float2*)p0 = o0;
            *(float2*)(p0 + 8 * N) = o1;
        }
    }
}

// ---------------- radix-4 FFT attention, 2 rows per block ----------------
__device__ __forceinline__ int rev4(int v) {
    return ((v & 3) << 8) | (((v >> 2) & 3) << 6) | (((v >> 4) & 3) << 4)
         | (((v >> 6) & 3) << 2) | ((v >> 8) & 3);
}

__device__ __forceinline__ void fft1024_r4(float2* s, const float2* Tw, int tid, bool inv) {
    #pragma unroll
    for (int stage = 0; stage < 5; ++stage) {
        const int q = 1 << (2 * stage);
        const int j = tid & (q - 1);
        const int grp = tid >> (2 * stage);
        const int i0 = grp * (q << 2) + j;
        const int i1 = i0 + q, i2 = i1 + q, i3 = i2 + q;

        float2 w1 = Tw[j << (8 - 2 * stage)];
        if (inv) w1.y = -w1.y;
        float2 w2 = cmulf(w1, w1);
        float2 w3 = cmulf(w1, w2);

        float2 a = s[i0];
        float2 b = cmulf(s[i1], w1);
        float2 c = cmulf(s[i2], w2);
        float2 d = cmulf(s[i3], w3);

        float2 acp = make_float2(a.x + c.x, a.y + c.y);
        float2 acm = make_float2(a.x - c.x, a.y - c.y);
        float2 bdp = make_float2(b.x + d.x, b.y + d.y);
        float2 bdm = make_float2(b.x - d.x, b.y - d.y);
        float2 ib = inv ? make_float2(-bdm.y, bdm.x) : make_float2(bdm.y, -bdm.x);

        s[i0] = make_float2(acp.x + bdp.x, acp.y + bdp.y);
        s[i1] = make_float2(acm.x + ib.x,  acm.y + ib.y);
        s[i2] = make_float2(acp.x - bdp.x, acp.y - bdp.y);
        s[i3] = make_float2(acm.x - ib.x,  acm.y - ib.y);
        __syncthreads();
    }
}

__global__ __launch_bounds__(256) void fft_attn_kernel(
    const float* __restrict__ Q, const float* __restrict__ Kx,
    const float* __restrict__ V,
    __half* __restrict__ Oh, __half* __restrict__ Om)
{
    __shared__ float2 Z[1024];
    __shared__ float2 A0[1024];
    __shared__ float2 A1[1024];
    __shared__ float2 Tw[256];
    const int row0 = blockIdx.x * 2;
    const int row1 = row0 + 1;
    const int tid = threadIdx.x;
    const float* q0 = Q  + (size_t)row0 * Pd;
    const float* k0 = Kx + (size_t)row0 * Pd;
    const float* q1 = Q  + (size_t)row1 * Pd;
    const float* k1 = Kx + (size_t)row1 * Pd;
    const float* v0 = V  + (size_t)row0 * Pd;
    const float* v1 = V  + (size_t)row1 * Pd;

    {
        float sn, cs;
        __sincosf(-6.283185307179586f * (float)tid / 1024.0f, &sn, &cs);
        Tw[tid] = make_float2(cs, sn);
    }

    const float inv_scale = 1.0f / 32.0f;

    #pragma unroll
    for (int u = 0; u < 4; u++) {
        int i = tid + u * 256;
        Z[rev4(i)] = make_float2(q0[i], k0[i]);
    }
    __syncthreads();
    fft1024_r4(Z, Tw, tid, false);
    #pragma unroll
    for (int u = 0; u < 4; u++) {
        int i = tid + u * 256;
        float2 zj = Z[i];
        float2 zn = Z[(1024 - i) & 1023];
        float Qx = 0.5f * (zj.x + zn.x), Qy = 0.5f * (zj.y - zn.y);
        float Kxr = 0.5f * (zj.y + zn.y), Kyr = -0.5f * (zj.x - zn.x);
        A0[i] = make_float2((Kxr * Qx + Kyr * Qy) * inv_scale,
                            (Kyr * Qx - Kxr * Qy) * inv_scale);
    }
    __syncthreads();

    #pragma unroll
    for (int u = 0; u < 4; u++) {
        int i = tid + u * 256;
        Z[rev4(i)] = make_float2(q1[i], k1[i]);
    }
    __syncthreads();
    fft1024_r4(Z, Tw, tid, false);
    #pragma unroll
    for (int u = 0; u < 4; u++) {
        int i = tid + u * 256;
        float2 zj = Z[i];
        float2 zn = Z[(1024 - i) & 1023];
        float Qx = 0.5f * (zj.x + zn.x), Qy = 0.5f * (zj.y - zn.y);
        float Kxr = 0.5f * (zj.y + zn.y), Kyr = -0.5f * (zj.x - zn.x);
        A1[i] = make_float2((Kxr * Qx + Kyr * Qy) * inv_scale,
                            (Kyr * Qx - Kxr * Qy) * inv_scale);
    }
    __syncthreads();

    #pragma unroll
    for (int u = 0; u < 4; u++) {
        int i = tid + u * 256;
        Z[rev4(i)] = make_float2(v0[i], v1[i]);
    }
    __syncthreads();
    fft1024_r4(Z, Tw, tid, false);
    #pragma unroll
    for (int u = 0; u < 4; u++) {
        int i = tid + u * 256;
        float2 zj = Z[i];
        float2 zn = Z[(1024 - i) & 1023];
        float2 V0 = make_float2(0.5f * (zj.x + zn.x), 0.5f * (zj.y - zn.y));
        float2 V1 = make_float2(0.5f * (zj.y + zn.y), -0.5f * (zj.x - zn.x));
        A0[i] = cmulf(A0[i], V0);
        A1[i] = cmulf(A1[i], V1);
    }
    __syncthreads();

    #pragma unroll
    for (int u = 0; u < 4; u++) {
        int i = tid + u * 256;
        int ni = (1024 - i) & 1023;
        float2 w0 = A0[i], w0n = A0[ni];
        float2 w1 = A1[i], w1n = A1[ni];
        float2 S0 = make_float2(0.5f * (w0.x + w0n.x), 0.5f * (w0.y - w0n.y));
        float2 S1 = make_float2(0.5f * (w1.x + w1n.x), 0.5f * (w1.y - w1n.y));
        Z[rev4(i)] = make_float2(S0.x - S1.y, S0.y + S1.x);
    }
    __syncthreads();
    fft1024_r4(Z, Tw, tid, true);

    __half* oh0 = Oh + (size_t)row0 * Pd;
    __half* om0 = Om + (size_t)row0 * Pd;
    __half* oh1 = Oh + (size_t)row1 * Pd;
    __half* om1 = Om + (size_t)row1 * Pd;
    const float invN = 1.0f / 1024.0f;
    #pragma unroll
    for (int u = 0; u < 4; u++) {
        int i = tid + u * 256;
        float s0 = Z[i].x * invN;
        float s1 = Z[i].y * invN;
        __half h0, m0, h1, m1;
        split2h(s0, h0, m0);
        split2h(s1, h1, m1);
        oh0[i] = h0; om0[i] = m0;
        oh1[i] = h1; om1[i] = m1;
    }
}

// ---------------- launch ----------------
extern "C" void kernel_launch(void* const* d_in, const int* in_sizes, int n_in,
                              void* d_out, int out_size) {
    (void)in_sizes; (void)n_in; (void)out_size;
    const float* x      = (const float*)d_in[0];
    const float* conv_w = (const float*)d_in[1];
    const float* conv_b = (const float*)d_in[2];
    const float* wq     = (const float*)d_in[3];
    const float* bq     = (const float*)d_in[4];
    const float* wk     = (const float*)d_in[5];
    const float* bk     = (const float*)d_in[6];
    const float* wv     = (const float*)d_in[7];
    const float* bv     = (const float*)d_in[8];
    const float* wo     = (const float*)d_in[9];
    const float* bo     = (const float*)d_in[10];
    float* out = (float*)d_out;

    float *xb, *qkv, *bqkv, *wavg, *bavg;
    __half *ch, *cm, *ph, *pm, *wqkvh, *woh;
    cudaGetSymbolAddress((void**)&xb,    g_x);
    cudaGetSymbolAddress((void**)&ch,    g_ch);
    cudaGetSymbolAddress((void**)&cm,    g_cm);
    cudaGetSymbolAddress((void**)&qkv,   g_qkv);
    cudaGetSymbolAddress((void**)&ph,    g_ph);
    cudaGetSymbolAddress((void**)&pm,    g_pm);
    cudaGetSymbolAddress((void**)&wqkvh, g_wqkv);
    cudaGetSymbolAddress((void**)&woh,   g_wo);
    cudaGetSymbolAddress((void**)&bqkv,  g_bqkv);
    cudaGetSymbolAddress((void**)&wavg,  g_wavg);
    cudaGetSymbolAddress((void**)&bavg,  g_bavg);

    cudaFuncSetAttribute(gemm_mma_kernel,
                         cudaFuncAttributeMaxDynamicSharedMemorySize, GEMM_SMEM);

    const size_t LPW = (size_t)Ld * Pd * Wd;   // 4M elements

    avg_conv_kernel<<<1, 64>>>(conv_w, conv_b, wavg, bavg);

    cvt16_all_kernel<<<2048, 256>>>(wq, wk, wv, wo, wqkvh, woh, (int)(LPW / 8));

    cudaMemcpyAsync(bqkv,               bq, Ld * Pd * 4, cudaMemcpyDeviceToDevice);
    cudaMemcpyAsync(bqkv + Ld * Pd,     bk, Ld * Pd * 4, cudaMemcpyDeviceToDevice);
    cudaMemcpyAsync(bqkv + 2 * Ld * Pd, bv, Ld * Pd * 4, cudaMemcpyDeviceToDevice);

    const size_t RP = (size_t)ROWS * Pd;

    for (int l = 0; l < Ld; l++) {
        const float* xin = (l == 0) ? x : xb;
        float* xout = (l == Ld - 1) ? out : xb;

        conv_row_kernel<<<ROWS, 256>>>(xin, ch, cm, wavg + l * Kc, bavg + l);

        dim3 gq(Pd / 128, ROWS / 128, 3);     // (8, 32, 3)
        gemm_mma_kernel<<<gq, 256, GEMM_SMEM>>>(
            ch, cm,
            wqkvh + (size_t)l * Pd * Wd,
            bqkv + (size_t)l * Pd, qkv,
            Wd, Pd, LPW, (size_t)Ld * Pd, RP);

        fft_attn_kernel<<<ROWS / 2, 256>>>(qkv, qkv + RP, qkv + 2 * RP, ph, pm);

        dim3 go(Wd / 128, ROWS / 128, 1);     // (16, 32, 1)
        gemm_mma_kernel<<<go, 256, GEMM_SMEM>>>(
            ph, pm,
            woh + (size_t)l * Wd * Pd,
            bo + (size_t)l * Wd, xout,
            Pd, Wd, 0, 0, 0);
    }
}

// round 16
// speedup vs baseline: 1.1975x; 1.0162x over previous
#include <cuda_runtime.h>
#include <cuda_fp16.h>
#include <cstdint>

#define BSZ 32
#define CNT 128
#define Wd  2048
#define Pd  1024
#define Ed  8
#define Kc  25
#define Ld  2
#define ROWS (BSZ*CNT)   // 4096

// ---------------- scratch ----------------
__device__ float  g_x[ROWS*Wd];
__device__ __half g_ch[ROWS*Wd];
__device__ __half g_cm[ROWS*Wd];
__device__ float  g_qkv[3*ROWS*Pd];
__device__ __half g_ph[ROWS*Pd];
__device__ __half g_pm[ROWS*Pd];
__device__ __half g_wqkv[3*Ld*Pd*Wd];
__device__ __half g_wo[Ld*Wd*Pd];
__device__ float  g_bqkv[3*Ld*Pd];
__device__ float  g_wavg[Ld*Kc];
__device__ float  g_bavg[Ld];

// ---------------- helpers ----------------
__device__ __forceinline__ uint32_t smem_u32(const void* p) {
    uint32_t a;
    asm("{ .reg .u64 t; cvta.to.shared.u64 t, %1; cvt.u32.u64 %0, t; }" : "=r"(a) : "l"(p));
    return a;
}
__device__ __forceinline__ void cp16(uint32_t dst, const void* src) {
    asm volatile("cp.async.cg.shared.global [%0], [%1], 16;" :: "r"(dst), "l"(src));
}
__device__ __forceinline__ void split2h(float x, __half& h, __half& m) {
    h = __float2half(x);
    m = __float2half(x - __half2float(h));
}
__device__ __forceinline__ uint32_t pack2h(__half a, __half b) {
    return (uint32_t)__half_as_ushort(a) | ((uint32_t)__half_as_ushort(b) << 16);
}
__device__ __forceinline__ float2 cmulf(float2 a, float2 b) {
    return make_float2(a.x * b.x - a.y * b.y, a.x * b.y + a.y * b.x);
}

// ---------------- weight convert fp32 -> fp16 (all 4 matrices, one launch) ----------------
__global__ void cvt16_all_kernel(const float* __restrict__ wq, const float* __restrict__ wk,
                                 const float* __restrict__ wv, const float* __restrict__ wo,
                                 __half* __restrict__ wqkv, __half* __restrict__ wod, int n8) {
    int i = blockIdx.x * blockDim.x + threadIdx.x;
    int stride = gridDim.x * blockDim.x;
    for (; i < 4 * n8; i += stride) {
        int sel = i / n8, j = i - sel * n8;
        const float* src = (sel == 0) ? wq : (sel == 1) ? wk : (sel == 2) ? wv : wo;
        __half* dst = (sel < 3) ? (wqkv + (size_t)sel * n8 * 8) : wod;
        float4 v0 = ((const float4*)src)[2 * j];
        float4 v1 = ((const float4*)src)[2 * j + 1];
        uint4 u;
        u.x = pack2h(__float2half(v0.x), __float2half(v0.y));
        u.y = pack2h(__float2half(v0.z), __float2half(v0.w));
        u.z = pack2h(__float2half(v1.x), __float2half(v1.y));
        u.w = pack2h(__float2half(v1.z), __float2half(v1.w));
        ((uint4*)dst)[j] = u;
    }
}

// ---------------- avg conv weights ----------------
__global__ void avg_conv_kernel(const float* __restrict__ cw, const float* __restrict__ cb,
                                float* __restrict__ wavg, float* __restrict__ bavg) {
    int idx = threadIdx.x;
    if (idx < Ld * Kc) {
        int l = idx / Kc, kk = idx % Kc;
        float s = 0.f;
        #pragma unroll
        for (int e = 0; e < Ed; e++) s += cw[(l * Ed + e) * Kc + kk];
        wavg[idx] = s * (1.0f / Ed);
    }
    if (idx < Ld) {
        float s = 0.f;
        #pragma unroll
        for (int e = 0; e < Ed; e++) s += cb[idx * Ed + e];
        bavg[idx] = s * (1.0f / Ed);
    }
}

// ---------------- 1D conv, writes fp16 h/m ----------------
__global__ __launch_bounds__(256) void conv_row_kernel(
    const float* __restrict__ X, __half* __restrict__ Yh, __half* __restrict__ Ym,
    const float* __restrict__ wavg, const float* __restrict__ bavg)
{
    __shared__ float sx[Wd + Kc - 1];
    __shared__ float wsh[Kc];
    const int row = blockIdx.x;
    const int tid = threadIdx.x;
    const float* xr = X + (size_t)row * Wd;

    for (int i = tid; i < Wd + Kc - 1; i += 256) {
        int src = i - (Kc / 2);
        sx[i] = (src >= 0 && src < Wd) ? xr[src] : 0.0f;
    }
    if (tid < Kc) wsh[tid] = wavg[tid];
    __syncthreads();

    const float b = bavg[0];
    __half* yh = Yh + (size_t)row * Wd;
    __half* ym = Ym + (size_t)row * Wd;
    for (int h = tid; h < Wd; h += 256) {
        float s = b;
        #pragma unroll
        for (int k = 0; k < Kc; k++) s += sx[h + k] * wsh[k];
        __half sh, sm_;
        split2h(s, sh, sm_);
        yh[h] = sh; ym[h] = sm_;
    }
}

// ---------------- fp16x2 mma.sync GEMM, BK=64, 2-stage, 1 sync/chunk ----------------
#define MMA16(cc, aa, bb) \
    asm volatile("mma.sync.aligned.m16n8k16.row.col.f32.f16.f16.f32 " \
        "{%0,%1,%2,%3},{%4,%5,%6,%7},{%8,%9},{%0,%1,%2,%3};" \
        : "+f"((cc)[0]), "+f"((cc)[1]), "+f"((cc)[2]), "+f"((cc)[3]) \
        : "r"((aa)[0]), "r"((aa)[1]), "r"((aa)[2]), "r"((aa)[3]), \
          "r"((bb)[0]), "r"((bb)[1]))

#define LDMX4(r0, r1, r2, r3, a) \
    asm volatile("ldmatrix.sync.aligned.m8n8.x4.shared.b16 {%0,%1,%2,%3}, [%4];" \
        : "=r"(r0), "=r"(r1), "=r"(r2), "=r"(r3) : "r"(a))

#define BK 64
#define TILE_B 16384           // 128 rows x 128 bytes (64 fp16), swizzled
#define STAGE_B (3*TILE_B)     // Ah, Am, W = 48KB
#define GEMM_SMEM (2*STAGE_B)  // 98304 bytes

__global__ __launch_bounds__(256, 2) void gemm_mma_kernel(
    const __half* __restrict__ Ah, const __half* __restrict__ Am,
    const __half* __restrict__ Bw,
    const float* __restrict__ bias, float* __restrict__ C,
    int Kd, int N, size_t szB, size_t szBias, size_t szC)
{
    extern __shared__ uint32_t sm[];
    const uint32_t sbase = smem_u32(sm);
    const int z = blockIdx.z;
    Bw   += (size_t)z * szB;
    bias += (size_t)z * szBias;
    C    += (size_t)z * szC;

    const int tid = threadIdx.x;
    const int wid = tid >> 5, lane = tid & 31;
    const int g = lane >> 2, t = lane & 3;
    const int wm = (wid >> 1) * 32;       // 4 m-groups x 32 rows
    const int wn = (wid & 1) * 64;        // 2 n-groups x 64 cols
    const int bm = blockIdx.y * 128, bn = blockIdx.x * 128;
    const int stA = wid & 1;

    // ---- ldmatrix per-lane byte offsets, 4 k-substeps ----
    const int lr = lane & 7;
    const int ls = lane >> 3;   // 0..3
    uint32_t Abase[4], Bbase[4];
    #pragma unroll
    for (int st = 0; st < 4; st++) {
        int arow = wm + lr + (ls & 1) * 8;
        int agrp = st * 2 + (ls >> 1);
        Abase[st] = (uint32_t)(arow * 128 + ((agrp ^ (arow & 7)) << 4));
        int brow = wn + (ls >> 1) * 8 + lr;
        int bgrp = st * 2 + (ls & 1);
        Bbase[st] = (uint32_t)(brow * 128 + ((bgrp ^ (brow & 7)) << 4));
    }

    // cp.async mapping: 1024 groups/plane, 4 per thread (j*32 rows apart)
    const int crow = tid >> 3;            // 0..31
    const int cg = tid & 7;               // group 0..7
    const uint32_t sg = (uint32_t)(cg ^ (crow & 7));
    uint32_t cdst[4];
    #pragma unroll
    for (int j = 0; j < 4; j++)
        cdst[j] = (uint32_t)((crow + j * 32) * 128) + (sg << 4);

    const __half* pAh = Ah + (size_t)(bm + crow) * Kd + cg * 8;
    const __half* pAm = Am + (size_t)(bm + crow) * Kd + cg * 8;
    const __half* pBw = Bw + (size_t)(bn + crow) * Kd + cg * 8;
    const size_t rstep = (size_t)32 * Kd;

    float acc[2][8][4];
    #pragma unroll
    for (int mt = 0; mt < 2; mt++)
        #pragma unroll
        for (int nt = 0; nt < 8; nt++)
            #pragma unroll
            for (int e = 0; e < 4; e++) acc[mt][nt][e] = 0.0f;

    const int NC = Kd / BK;

    #define ISSUE(s, kpos) do { \
        uint32_t _sb = sbase + (uint32_t)(s) * STAGE_B; \
        _Pragma("unroll") \
        for (int j = 0; j < 4; j++) { \
            cp16(_sb + cdst[j],              pAh + j * rstep + (kpos)); \
            cp16(_sb + TILE_B + cdst[j],     pAm + j * rstep + (kpos)); \
            cp16(_sb + 2 * TILE_B + cdst[j], pBw + j * rstep + (kpos)); \
        } \
        asm volatile("cp.async.commit_group;" ::: "memory"); \
    } while (0)

    ISSUE(0, 0);

    for (int i = 0; i < NC; i++) {
        // wait for ALL outstanding copies (stage i&1 now full for this thread)
        asm volatile("cp.async.wait_group 0;" ::: "memory");
        // single barrier: (a) all threads' copies visible; (b) all warps done
        // with previous chunk's reads of stage (i+1)&1 -> safe to overwrite
        __syncthreads();
        if (i + 1 < NC) ISSUE((i + 1) & 1, (i + 1) * BK);

        const uint32_t sAh = sbase + (uint32_t)(i & 1) * STAGE_B;
        const uint32_t sAm = sAh + TILE_B;
        const uint32_t sBw = sAm + TILE_B;

        #pragma unroll
        for (int s = 0; s < 4; s++) {
            const int st = s ^ stA;
            const uint32_t ab = Abase[st];
            const uint32_t bb = Bbase[st];

            uint32_t bw[8][2];
            LDMX4(bw[0][0], bw[0][1], bw[1][0], bw[1][1], sBw + bb);
            LDMX4(bw[2][0], bw[2][1], bw[3][0], bw[3][1], sBw + bb + 2048);
            LDMX4(bw[4][0], bw[4][1], bw[5][0], bw[5][1], sBw + bb + 4096);
            LDMX4(bw[6][0], bw[6][1], bw[7][0], bw[7][1], sBw + bb + 6144);

            #pragma unroll
            for (int mt = 0; mt < 2; mt++) {
                uint32_t ah[4], am_[4];
                uint32_t ao = ab + (uint32_t)mt * 2048;
                LDMX4(ah[0], ah[1], ah[2], ah[3], sAh + ao);
                LDMX4(am_[0], am_[1], am_[2], am_[3], sAm + ao);
                #pragma unroll
                for (int nt = 0; nt < 8; nt++) {
                    MMA16(acc[mt][nt], ah,  bw[nt]);
                    MMA16(acc[mt][nt], am_, bw[nt]);
                }
            }
        }
    }
    #undef ISSUE

    #pragma unroll
    for (int mt = 0; mt < 2; mt++) {
        #pragma unroll
        for (int nt = 0; nt < 8; nt++) {
            int col = bn + wn + nt * 8 + 2 * t;
            float b0 = __ldg(&bias[col]);
            float b1 = __ldg(&bias[col + 1]);
            float* p0 = C + (size_t)(bm + wm + mt * 16 + g) * N + col;
            float2 o0 = make_float2(acc[mt][nt][0] + b0, acc[mt][nt][1] + b1);
            float2 o1 = make_float2(acc[mt][nt][2] + b0, acc[mt][nt][3] + b1);
            *(float2*)p0 = o0;
            *(float2*)(p0 + 8 * N) = o1;
        }
    }
}

// ---------------- radix-4 FFT attention, 2 rows per block ----------------
__device__ __forceinline__ int rev4(int v) {
    return ((v & 3) << 8) | (((v >> 2) & 3) << 6) | (((v >> 4) & 3) << 4)
         | (((v >> 6) & 3) << 2) | ((v >> 8) & 3);
}

__device__ __forceinline__ void fft1024_r4(float2* s, const float2* Tw, int tid, bool inv) {
    #pragma unroll
    for (int stage = 0; stage < 5; ++stage) {
        const int q = 1 << (2 * stage);
        const int j = tid & (q - 1);
        const int grp = tid >> (2 * stage);
        const int i0 = grp * (q << 2) + j;
        const int i1 = i0 + q, i2 = i1 + q, i3 = i2 + q;

        float2 w1 = Tw[j << (8 - 2 * stage)];
        if (inv) w1.y = -w1.y;
        float2 w2 = cmulf(w1, w1);
        float2 w3 = cmulf(w1, w2);

        float2 a = s[i0];
        float2 b = cmulf(s[i1], w1);
        float2 c = cmulf(s[i2], w2);
        float2 d = cmulf(s[i3], w3);

        float2 acp = make_float2(a.x + c.x, a.y + c.y);
        float2 acm = make_float2(a.x - c.x, a.y - c.y);
        float2 bdp = make_float2(b.x + d.x, b.y + d.y);
        float2 bdm = make_float2(b.x - d.x, b.y - d.y);
        float2 ib = inv ? make_float2(-bdm.y, bdm.x) : make_float2(bdm.y, -bdm.x);

        s[i0] = make_float2(acp.x + bdp.x, acp.y + bdp.y);
        s[i1] = make_float2(acm.x + ib.x,  acm.y + ib.y);
        s[i2] = make_float2(acp.x - bdp.x, acp.y - bdp.y);
        s[i3] = make_float2(acm.x - ib.x,  acm.y - ib.y);
        __syncthreads();
    }
}

__global__ __launch_bounds__(256) void fft_attn_kernel(
    const float* __restrict__ Q, const float* __restrict__ Kx,
    const float* __restrict__ V,
    __half* __restrict__ Oh, __half* __restrict__ Om)
{
    __shared__ float2 Z[1024];
    __shared__ float2 A0[1024];
    __shared__ float2 A1[1024];
    __shared__ float2 Tw[256];
    const int row0 = blockIdx.x * 2;
    const int row1 = row0 + 1;
    const int tid = threadIdx.x;
    const float* q0 = Q  + (size_t)row0 * Pd;
    const float* k0 = Kx + (size_t)row0 * Pd;
    const float* q1 = Q  + (size_t)row1 * Pd;
    const float* k1 = Kx + (size_t)row1 * Pd;
    const float* v0 = V  + (size_t)row0 * Pd;
    const float* v1 = V  + (size_t)row1 * Pd;

    {
        float sn, cs;
        __sincosf(-6.283185307179586f * (float)tid / 1024.0f, &sn, &cs);
        Tw[tid] = make_float2(cs, sn);
    }

    const float inv_scale = 1.0f / 32.0f;

    #pragma unroll
    for (int u = 0; u < 4; u++) {
        int i = tid + u * 256;
        Z[rev4(i)] = make_float2(q0[i], k0[i]);
    }
    __syncthreads();
    fft1024_r4(Z, Tw, tid, false);
    #pragma unroll
    for (int u = 0; u < 4; u++) {
        int i = tid + u * 256;
        float2 zj = Z[i];
        float2 zn = Z[(1024 - i) & 1023];
        float Qx = 0.5f * (zj.x + zn.x), Qy = 0.5f * (zj.y - zn.y);
        float Kxr = 0.5f * (zj.y + zn.y), Kyr = -0.5f * (zj.x - zn.x);
        A0[i] = make_float2((Kxr * Qx + Kyr * Qy) * inv_scale,
                            (Kyr * Qx - Kxr * Qy) * inv_scale);
    }
    __syncthreads();

    #pragma unroll
    for (int u = 0; u < 4; u++) {
        int i = tid + u * 256;
        Z[rev4(i)] = make_float2(q1[i], k1[i]);
    }
    __syncthreads();
    fft1024_r4(Z, Tw, tid, false);
    #pragma unroll
    for (int u = 0; u < 4; u++) {
        int i = tid + u * 256;
        float2 zj = Z[i];
        float2 zn = Z[(1024 - i) & 1023];
        float Qx = 0.5f * (zj.x + zn.x), Qy = 0.5f * (zj.y - zn.y);
        float Kxr = 0.5f * (zj.y + zn.y), Kyr = -0.5f * (zj.x - zn.x);
        A1[i] = make_float2((Kxr * Qx + Kyr * Qy) * inv_scale,
                            (Kyr * Qx - Kxr * Qy) * inv_scale);
    }
    __syncthreads();

    #pragma unroll
    for (int u = 0; u < 4; u++) {
        int i = tid + u * 256;
        Z[rev4(i)] = make_float2(v0[i], v1[i]);
    }
    __syncthreads();
    fft1024_r4(Z, Tw, tid, false);
    #pragma unroll
    for (int u = 0; u < 4; u++) {
        int i = tid + u * 256;
        float2 zj = Z[i];
        float2 zn = Z[(1024 - i) & 1023];
        float2 V0 = make_float2(0.5f * (zj.x + zn.x), 0.5f * (zj.y - zn.y));
        float2 V1 = make_float2(0.5f * (zj.y + zn.y), -0.5f * (zj.x - zn.x));
        A0[i] = cmulf(A0[i], V0);
        A1[i] = cmulf(A1[i], V1);
    }
    __syncthreads();

    #pragma unroll
    for (int u = 0; u < 4; u++) {
        int i = tid + u * 256;
        int ni = (1024 - i) & 1023;
        float2 w0 = A0[i], w0n = A0[ni];
        float2 w1 = A1[i], w1n = A1[ni];
        float2 S0 = make_float2(0.5f * (w0.x + w0n.x), 0.5f * (w0.y - w0n.y));
        float2 S1 = make_float2(0.5f * (w1.x + w1n.x), 0.5f * (w1.y - w1n.y));
        Z[rev4(i)] = make_float2(S0.x - S1.y, S0.y + S1.x);
    }
    __syncthreads();
    fft1024_r4(Z, Tw, tid, true);

    __half* oh0 = Oh + (size_t)row0 * Pd;
    __half* om0 = Om + (size_t)row0 * Pd;
    __half* oh1 = Oh + (size_t)row1 * Pd;
    __half* om1 = Om + (size_t)row1 * Pd;
    const float invN = 1.0f / 1024.0f;
    #pragma unroll
    for (int u = 0; u < 4; u++) {
        int i = tid + u * 256;
        float s0 = Z[i].x * invN;
        float s1 = Z[i].y * invN;
        __half h0, m0, h1, m1;
        split2h(s0, h0, m0);
        split2h(s1, h1, m1);
        oh0[i] = h0; om0[i] = m0;
        oh1[i] = h1; om1[i] = m1;
    }
}

// ---------------- launch ----------------
extern "C" void kernel_launch(void* const* d_in, const int* in_sizes, int n_in,
                              void* d_out, int out_size) {
    (void)in_sizes; (void)n_in; (void)out_size;
    const float* x      = (const float*)d_in[0];
    const float* conv_w = (const float*)d_in[1];
    const float* conv_b = (const float*)d_in[2];
    const float* wq     = (const float*)d_in[3];
    const float* bq     = (const float*)d_in[4];
    const float* wk     = (const float*)d_in[5];
    const float* bk     = (const float*)d_in[6];
    const float* wv     = (const float*)d_in[7];
    const float* bv     = (const float*)d_in[8];
    const float* wo     = (const float*)d_in[9];
    const float* bo     = (const float*)d_in[10];
    float* out = (float*)d_out;

    float *xb, *qkv, *bqkv, *wavg, *bavg;
    __half *ch, *cm, *ph, *pm, *wqkvh, *woh;
    cudaGetSymbolAddress((void**)&xb,    g_x);
    cudaGetSymbolAddress((void**)&ch,    g_ch);
    cudaGetSymbolAddress((void**)&cm,    g_cm);
    cudaGetSymbolAddress((void**)&qkv,   g_qkv);
    cudaGetSymbolAddress((void**)&ph,    g_ph);
    cudaGetSymbolAddress((void**)&pm,    g_pm);
    cudaGetSymbolAddress((void**)&wqkvh, g_wqkv);
    cudaGetSymbolAddress((void**)&woh,   g_wo);
    cudaGetSymbolAddress((void**)&bqkv,  g_bqkv);
    cudaGetSymbolAddress((void**)&wavg,  g_wavg);
    cudaGetSymbolAddress((void**)&bavg,  g_bavg);

    cudaFuncSetAttribute(gemm_mma_kernel,
                         cudaFuncAttributeMaxDynamicSharedMemorySize, GEMM_SMEM);

    const size_t LPW = (size_t)Ld * Pd * Wd;   // 4M elements

    avg_conv_kernel<<<1, 64>>>(conv_w, conv_b, wavg, bavg);

    cvt16_all_kernel<<<2048, 256>>>(wq, wk, wv, wo, wqkvh, woh, (int)(LPW / 8));

    cudaMemcpyAsync(bqkv,               bq, Ld * Pd * 4, cudaMemcpyDeviceToDevice);
    cudaMemcpyAsync(bqkv + Ld * Pd,     bk, Ld * Pd * 4, cudaMemcpyDeviceToDevice);
    cudaMemcpyAsync(bqkv + 2 * Ld * Pd, bv, Ld * Pd * 4, cudaMemcpyDeviceToDevice);

    const size_t RP = (size_t)ROWS * Pd;

    for (int l = 0; l < Ld; l++) {
        const float* xin = (l == 0) ? x : xb;
        float* xout = (l == Ld - 1) ? out : xb;

        conv_row_kernel<<<ROWS, 256>>>(xin, ch, cm, wavg + l * Kc, bavg + l);

        dim3 gq(Pd / 128, ROWS / 128, 3);     // (8, 32, 3)
        gemm_mma_kernel<<<gq, 256, GEMM_SMEM>>>(
            ch, cm,
            wqkvh + (size_t)l * Pd * Wd,
            bqkv + (size_t)l * Pd, qkv,
            Wd, Pd, LPW, (size_t)Ld * Pd, RP);

        fft_attn_kernel<<<ROWS / 2, 256>>>(qkv, qkv + RP, qkv + 2 * RP, ph, pm);

        dim3 go(Wd / 128, ROWS / 128, 1);     // (16, 32, 1)
        gemm_mma_kernel<<<go, 256, GEMM_SMEM>>>(
            ph, pm,
            woh + (size_t)l * Wd * Pd,
            bo + (size_t)l * Wd, xout,
            Pd, Wd, 0, 0, 0);
    }
}